// round 3
// baseline (speedup 1.0000x reference)
#include <cuda_runtime.h>
#include <cstdint>

// x: (B=8, C=16, T=2000, F=128) fp32.
// Per (b,c,f) column: POOL=10 block sums, causal cumulative mean/var, normalize.
// Single pass. cp.async ring buffer (depth 20 pooled blocks) in shared memory;
// grid = 128 columns x 4 f-quarters = 512 CTAs of 32 threads (1 warp each).
// In-flight = 512 warps * 19 stages * 1.25KB ~= 12 MB -> HBM saturation.

#define TT    2000
#define FF    128
#define PP    10
#define TT1   200
#define DD    20         // ring depth in pooled blocks (divides TT1)
#define EPSV  1e-5f

__device__ __forceinline__ void cp4(uint32_t saddr, const float* gaddr) {
    asm volatile("cp.async.ca.shared.global [%0], [%1], 4;\n"
                 :: "r"(saddr), "l"(gaddr));
}
#define CP_COMMIT() asm volatile("cp.async.commit_group;\n")
#define CP_WAIT(n)  asm volatile("cp.async.wait_group %0;\n" :: "n"(n))

__global__ void __launch_bounds__(32, 4)
inorm_kernel(const float* __restrict__ x, float* __restrict__ out)
{
    __shared__ float buf[DD][PP][32];   // 25600 B

    const int col  = blockIdx.x >> 2;                        // (b*C + c): 0..127
    const int f    = ((blockIdx.x & 3) << 5) + threadIdx.x;  // 0..127
    const int lane = threadIdx.x;

    const float* p = x   + (size_t)col * TT * FF + f;
    float*       o = out + (size_t)col * TT * FF + f;

    uint32_t sbase;
    asm("{ .reg .u64 t; cvta.to.shared.u64 t, %1; cvt.u32.u64 %0, t; }"
        : "=r"(sbase) : "l"(&buf[0][0][lane]));
    // byte strides: element i -> 128, stage -> PP*128 = 1280

    // Prologue: fill the ring with blocks 0..DD-1 (one commit group per stage)
    #pragma unroll
    for (int st = 0; st < DD; st++) {
        #pragma unroll
        for (int i = 0; i < PP; i++)
            cp4(sbase + st * 1280 + i * 128, p + (st * PP + i) * FF);
        CP_COMMIT();
    }

    float s = 0.f, s2 = 0.f;

    #pragma unroll 1
    for (int kk = 0; kk < TT1; kk += DD) {
        #pragma unroll
        for (int st = 0; st < DD; st++) {
            const int k = kk + st;

            // Ensure stage k (the oldest of DD pending groups) has landed.
            CP_WAIT(DD - 1);

            // Consume block k from its ring slot.
            float a[PP];
            #pragma unroll
            for (int i = 0; i < PP; i++)
                a[i] = buf[st][i][lane];

            // Refill this slot with block k+DD, then commit (always commit so
            // the pending-group count stays consistent in the tail).
            const int kn = k + DD;
            if (kn < TT1) {
                const float* pg = p + kn * PP * FF;
                #pragma unroll
                for (int i = 0; i < PP; i++)
                    cp4(sbase + st * 1280 + i * 128, pg + i * FF);
            }
            CP_COMMIT();

            // Block sums + causal running stats
            float bs = 0.f, bs2 = 0.f;
            #pragma unroll
            for (int i = 0; i < PP; i++) {
                bs  += a[i];
                bs2  = fmaf(a[i], a[i], bs2);
            }
            s  += bs;
            s2 += bs2;

            const float invn = __fdividef(1.0f, (float)((k + 1) * PP));
            const float m    = s  * invn;
            const float m2   = s2 * invn;
            const float v    = fmaf(-m, m, m2);
            const float r    = rsqrtf(v + EPSV);

            float* og = o + k * PP * FF;
            #pragma unroll
            for (int i = 0; i < PP; i++)
                og[i * FF] = (a[i] - m) * r;
        }
    }
}

extern "C" void kernel_launch(void* const* d_in, const int* in_sizes, int n_in,
                              void* d_out, int out_size)
{
    const float* x   = (const float*)d_in[0];
    float*       out = (float*)d_out;
    inorm_kernel<<<512, 32>>>(x, out);
}